// round 14
// baseline (speedup 1.0000x reference)
#include <cuda_runtime.h>
#include <cuda_fp16.h>

#define B_  4
#define S_  2048
#define N_  2048
#define D_  1024
#define H_  16
#define HD_ 64

// Scratch (allocation-free rule: __device__ globals)
__device__ __half g_qh[B_*H_*S_*HD_];  // LN'd, scaled 0.125*log2e, fp16
__device__ __half g_kh[B_*N_*HD_];     // LN'd K, fp16
__device__ __half g_vh[B_*N_*HD_];     // V fp16 (natural layout)
__device__ __half g_wh[D_*D_];         // proj W, fp16
__device__ __half g_oh[B_*H_*S_*HD_];  // attention output (B,H,S,HD) fp16
__device__ __half g_xh[B_*S_*D_];      // transposed + LN'd, fp16

// ---------------------------------------------------------------------------
// helpers
// ---------------------------------------------------------------------------
__device__ __forceinline__ float ex2(float x) {
    float y;
    asm("ex2.approx.ftz.f32 %0, %1;" : "=f"(y) : "f"(x));
    return y;
}
__device__ __forceinline__ unsigned packh2(float lo, float hi) {
    __half2 h = __floats2half2_rn(lo, hi);
    return *(unsigned*)&h;
}
__device__ __forceinline__ void mma_f16(float* c, const unsigned* a,
                                        unsigned b0, unsigned b1) {
    asm volatile(
        "mma.sync.aligned.m16n8k16.row.col.f32.f16.f16.f32 "
        "{%0,%1,%2,%3}, {%4,%5,%6,%7}, {%8,%9}, {%0,%1,%2,%3};"
        : "+f"(c[0]), "+f"(c[1]), "+f"(c[2]), "+f"(c[3])
        : "r"(a[0]), "r"(a[1]), "r"(a[2]), "r"(a[3]), "r"(b0), "r"(b1));
}
__device__ __forceinline__ void ldsm4(unsigned& r0, unsigned& r1, unsigned& r2,
                                      unsigned& r3, unsigned addr) {
    asm volatile("ldmatrix.sync.aligned.m8n8.x4.shared.b16 {%0,%1,%2,%3}, [%4];"
                 : "=r"(r0), "=r"(r1), "=r"(r2), "=r"(r3) : "r"(addr));
}
__device__ __forceinline__ void ldsm4t(unsigned& r0, unsigned& r1, unsigned& r2,
                                       unsigned& r3, unsigned addr) {
    asm volatile("ldmatrix.sync.aligned.m8n8.x4.trans.shared.b16 {%0,%1,%2,%3}, [%4];"
                 : "=r"(r0), "=r"(r1), "=r"(r2), "=r"(r3) : "r"(addr));
}
__device__ __forceinline__ void cp16(void* dst, const void* src) {
    unsigned d = (unsigned)__cvta_generic_to_shared(dst);
    asm volatile("cp.async.cg.shared.global [%0], [%1], 16;" :: "r"(d), "l"(src));
}
__device__ __forceinline__ void cp_commit() {
    asm volatile("cp.async.commit_group;");
}
template<int NN> __device__ __forceinline__ void cp_wait() {
    asm volatile("cp.async.wait_group %0;" :: "n"(NN));
}

// ---------------------------------------------------------------------------
// LN-64 row body: 16 lanes per row (float4/lane).
// ---------------------------------------------------------------------------
__device__ __forceinline__ void ln64_row(
    const float* __restrict__ x, __half* __restrict__ dst,
    const float* __restrict__ w, const float* __restrict__ bias,
    float scale, int row, int l16)
{
    float4 v = ((const float4*)(x + (size_t)row * 64))[l16];
    float s = v.x + v.y + v.z + v.w;
    #pragma unroll
    for (int m = 8; m; m >>= 1) s += __shfl_xor_sync(0xffffffffu, s, m);
    float mean = s * (1.0f / 64.0f);
    float a0 = v.x - mean, a1 = v.y - mean, a2 = v.z - mean, a3 = v.w - mean;
    float q2 = a0*a0 + a1*a1 + a2*a2 + a3*a3;
    #pragma unroll
    for (int m = 8; m; m >>= 1) q2 += __shfl_xor_sync(0xffffffffu, q2, m);
    float inv = rsqrtf(q2 * (1.0f / 64.0f) + 1e-5f);
    float4 wv = ((const float4*)w)[l16];
    float4 bv = ((const float4*)bias)[l16];
    uint2 o;
    o.x = packh2((a0 * inv * wv.x + bv.x) * scale, (a1 * inv * wv.y + bv.y) * scale);
    o.y = packh2((a2 * inv * wv.z + bv.z) * scale, (a3 * inv * wv.w + bv.w) * scale);
    ((uint2*)(dst + (size_t)row * 64))[l16] = o;
}

// ---------------------------------------------------------------------------
// Fused prep: Q-LN (8192 blocks) + K-LN (512) + V fp16 (256) + W fp16 (1024).
// ---------------------------------------------------------------------------
__global__ __launch_bounds__(256) void prep_kernel(
    const float* __restrict__ xq, const float* __restrict__ xk,
    const float* __restrict__ xv, const float* __restrict__ pw,
    const float* __restrict__ qn_w, const float* __restrict__ qn_b,
    const float* __restrict__ kn_w, const float* __restrict__ kn_b,
    float qscale)
{
    int blk = blockIdx.x;
    int tid = threadIdx.x;
    if (blk < 8192) {                           // Q LayerNorm: 131072 rows
        int row = blk * 16 + (tid >> 4);
        ln64_row(xq, g_qh, qn_w, qn_b, qscale, row, tid & 15);
    } else if (blk < 8704) {                    // K LayerNorm: 8192 rows
        int row = (blk - 8192) * 16 + (tid >> 4);
        ln64_row(xk, g_kh, kn_w, kn_b, 1.0f, row, tid & 15);
    } else if (blk < 8960) {                    // V f32->fp16: 131072 float4
        for (int i4 = (blk - 8704) * 256 + tid; i4 < B_*N_*HD_/4; i4 += 256 * 256) {
            float4 t = ((const float4*)xv)[i4];
            uint2 o;
            o.x = packh2(t.x, t.y);
            o.y = packh2(t.z, t.w);
            ((uint2*)g_vh)[i4] = o;
        }
    } else {                                    // W f32->fp16: 262144 float4
        int i4 = (blk - 8960) * 256 + tid;
        float4 t = ((const float4*)pw)[i4];
        uint2 o;
        o.x = packh2(t.x, t.y);
        o.y = packh2(t.z, t.w);
        ((uint2*)g_wh)[i4] = o;
    }
}

// ---------------------------------------------------------------------------
// Flash attention (R12 measured-best config): fp16 m16n8k16, 32 queries/warp,
// 4 warps / 128 threads, minBlocks=3, grid (S/128, B*H).
// Smem = 2 * 64*72*2 * 2 = 36864 B. fp16 output.
// ---------------------------------------------------------------------------
__global__ __launch_bounds__(128, 3) void attn_mma_kernel()
{
    __shared__ __half Ks[2][64][72];
    __shared__ __half Vs[2][64][72];

    int bh = blockIdx.y;
    int b  = bh >> 4;
    int tid  = threadIdx.x;
    int warp = tid >> 5, lane = tid & 31;
    int g = lane >> 2, tg = lane & 3;

    const __half* kp = g_kh + (size_t)b * N_ * 64;
    const __half* vp = g_vh + (size_t)b * N_ * 64;

    // Q fragments for 2 m16 blocks (rows warp*32 .. +31)
    const __half* qp = g_qh + ((size_t)bh * S_ + blockIdx.x * 128 + warp * 32) * 64;
    unsigned Qf[2][4][4];
    #pragma unroll
    for (int m = 0; m < 2; m++) {
        #pragma unroll
        for (int kt = 0; kt < 4; kt++) {
            Qf[m][kt][0] = *(const unsigned*)(qp + (size_t)(m*16 + g     ) * 64 + kt*16 + 2*tg);
            Qf[m][kt][1] = *(const unsigned*)(qp + (size_t)(m*16 + g + 8 ) * 64 + kt*16 + 2*tg);
            Qf[m][kt][2] = *(const unsigned*)(qp + (size_t)(m*16 + g     ) * 64 + kt*16 + 8 + 2*tg);
            Qf[m][kt][3] = *(const unsigned*)(qp + (size_t)(m*16 + g + 8 ) * 64 + kt*16 + 8 + 2*tg);
        }
    }

    float Oa[2][8][4];
    #pragma unroll
    for (int m = 0; m < 2; m++)
        #pragma unroll
        for (int i = 0; i < 8; i++)
            #pragma unroll
            for (int j = 0; j < 4; j++) Oa[m][i][j] = 0.0f;
    float La[2][4];
    #pragma unroll
    for (int m = 0; m < 2; m++)
        #pragma unroll
        for (int j = 0; j < 4; j++) La[m][j] = 0.0f;
    const unsigned ones_b = (g == 0) ? 0x3C003C00u : 0u;  // B[0][k]=1, else 0

    // staging: K/V = 64 rows x 8 x 16B chunks each (1024 cp16, 8/thread)
    auto stage = [&](int kc, int bb) {
        #pragma unroll
        for (int j = 0; j < 8; j++) {
            int i = tid + 128 * j;           // 0..1023
            if (i < 512) {
                int r = i >> 3, c = i & 7;
                cp16(&Ks[bb][r][c * 8], kp + ((size_t)kc * 64 + r) * 64 + c * 8);
            } else {
                int i2 = i - 512;
                int r = i2 >> 3, c = i2 & 7;
                cp16(&Vs[bb][r][c * 8], vp + ((size_t)kc * 64 + r) * 64 + c * 8);
            }
        }
        cp_commit();
    };

    stage(0, 0);
    int buf = 0;
    for (int kc = 0; kc < N_ / 64; kc++) {
        if (kc < N_ / 64 - 1) { stage(kc + 1, buf ^ 1); cp_wait<1>(); }
        else                  { cp_wait<0>(); }
        __syncthreads();

        unsigned ks_base = (unsigned)__cvta_generic_to_shared(&Ks[buf][0][0]);
        unsigned vs_base = (unsigned)__cvta_generic_to_shared(&Vs[buf][0][0]);

        // ---- S = Q @ K^T, processed in nt-pairs; ex2 + pack immediately.
        unsigned Pf[2][4][4];
        #pragma unroll
        for (int ntp = 0; ntp < 4; ntp++) {
            float sc[2][2][4];
            #pragma unroll
            for (int sub = 0; sub < 2; sub++) {
                int nt = ntp * 2 + sub;
                #pragma unroll
                for (int m = 0; m < 2; m++)
                    sc[m][sub][0] = sc[m][sub][1] = sc[m][sub][2] = sc[m][sub][3] = 0.0f;
                unsigned a0 = ks_base +
                    ((unsigned)((nt*8 + (lane & 7)) * 72 + (lane >> 3) * 8)) * 2;
                unsigned r0, r1, r2, r3;
                ldsm4(r0, r1, r2, r3, a0);            // kt0, kt1
                #pragma unroll
                for (int m = 0; m < 2; m++) {
                    mma_f16(sc[m][sub], Qf[m][0], r0, r1);
                    mma_f16(sc[m][sub], Qf[m][1], r2, r3);
                }
                ldsm4(r0, r1, r2, r3, a0 + 64);       // kt2, kt3
                #pragma unroll
                for (int m = 0; m < 2; m++) {
                    mma_f16(sc[m][sub], Qf[m][2], r0, r1);
                    mma_f16(sc[m][sub], Qf[m][3], r2, r3);
                }
            }
            // P = exp2(S) (no max: |S| <= 11.6); pack to fp16 A-frags
            #pragma unroll
            for (int m = 0; m < 2; m++) {
                #pragma unroll
                for (int sub = 0; sub < 2; sub++) {
                    sc[m][sub][0] = ex2(sc[m][sub][0]);
                    sc[m][sub][1] = ex2(sc[m][sub][1]);
                    sc[m][sub][2] = ex2(sc[m][sub][2]);
                    sc[m][sub][3] = ex2(sc[m][sub][3]);
                }
                Pf[m][ntp][0] = packh2(sc[m][0][0], sc[m][0][1]);
                Pf[m][ntp][1] = packh2(sc[m][0][2], sc[m][0][3]);
                Pf[m][ntp][2] = packh2(sc[m][1][0], sc[m][1][1]);
                Pf[m][ntp][3] = packh2(sc[m][1][2], sc[m][1][3]);
            }
        }

        // ---- rowsum l += P @ ones (tensor pipe)
        #pragma unroll
        for (int m = 0; m < 2; m++)
            #pragma unroll
            for (int kt = 0; kt < 4; kt++)
                mma_f16(La[m], Pf[m][kt], ones_b, ones_b);

        // ---- O += P @ V : V natural layout, ldmatrix.trans; B-frags shared by both m
        #pragma unroll
        for (int nt = 0; nt < 8; nt++) {
            unsigned a0 = vs_base +
                ((unsigned)(((lane >> 3) * 8 + (lane & 7)) * 72 + nt * 8)) * 2;
            unsigned r0, r1, r2, r3;
            ldsm4t(r0, r1, r2, r3, a0);                    // keys 0..31
            #pragma unroll
            for (int m = 0; m < 2; m++) {
                mma_f16(Oa[m][nt], Pf[m][0], r0, r1);
                mma_f16(Oa[m][nt], Pf[m][1], r2, r3);
            }
            ldsm4t(r0, r1, r2, r3, a0 + 32 * 72 * 2);      // keys 32..63
            #pragma unroll
            for (int m = 0; m < 2; m++) {
                mma_f16(Oa[m][nt], Pf[m][2], r0, r1);
                mma_f16(Oa[m][nt], Pf[m][3], r2, r3);
            }
        }
        __syncthreads();
        buf ^= 1;
    }

    // epilogue: broadcast rowsums within quads; normalize; fp16 store
    __half* op = g_oh + ((size_t)bh * S_ + blockIdx.x * 128 + warp * 32) * 64;
    #pragma unroll
    for (int m = 0; m < 2; m++) {
        float li0 = __shfl_sync(0xffffffffu, La[m][0], lane & ~3);
        float li1 = __shfl_sync(0xffffffffu, La[m][2], lane & ~3);
        float inv0 = 1.0f / li0, inv1 = 1.0f / li1;
        #pragma unroll
        for (int nt = 0; nt < 8; nt++) {
            unsigned v0 = packh2(Oa[m][nt][0] * inv0, Oa[m][nt][1] * inv0);
            unsigned v1 = packh2(Oa[m][nt][2] * inv1, Oa[m][nt][3] * inv1);
            *(unsigned*)(op + (size_t)(m*16 + g     ) * 64 + nt*8 + 2*tg) = v0;
            *(unsigned*)(op + (size_t)(m*16 + g + 8 ) * 64 + nt*8 + 2*tg) = v1;
        }
    }
}

// ---------------------------------------------------------------------------
// Gather fp16 (B,H,S,HD) -> (B,S,D) + LayerNorm over D=1024 -> fp16 output.
// ---------------------------------------------------------------------------
__global__ __launch_bounds__(256) void lnD_kernel(
    const float* __restrict__ w, const float* __restrict__ bias)
{
    int bs = blockIdx.x;
    int b = bs >> 11, s = bs & 2047;
    int tid = threadIdx.x;
    int d = tid * 4;
    int h = d >> 6, hd = d & 63;
    uint2 raw = *(const uint2*)(g_oh + (((size_t)(b * H_ + h) * S_ + s) * 64 + hd));
    float2 p0 = __half22float2(*(__half2*)&raw.x);
    float2 p1 = __half22float2(*(__half2*)&raw.y);
    float v0 = p0.x, v1 = p0.y, v2 = p1.x, v3 = p1.y;

    __shared__ float r1[8], r2[8];
    float sum = v0 + v1 + v2 + v3;
    #pragma unroll
    for (int m = 16; m; m >>= 1) sum += __shfl_xor_sync(0xffffffffu, sum, m);
    if ((tid & 31) == 0) r1[tid >> 5] = sum;
    __syncthreads();
    float tot = 0.0f;
    #pragma unroll
    for (int i = 0; i < 8; i++) tot += r1[i];
    float mean = tot * (1.0f / 1024.0f);

    float a0 = v0 - mean, a1 = v1 - mean, a2 = v2 - mean, a3 = v3 - mean;
    float sq = a0*a0 + a1*a1 + a2*a2 + a3*a3;
    #pragma unroll
    for (int m = 16; m; m >>= 1) sq += __shfl_xor_sync(0xffffffffu, sq, m);
    if ((tid & 31) == 0) r2[tid >> 5] = sq;
    __syncthreads();
    float tot2 = 0.0f;
    #pragma unroll
    for (int i = 0; i < 8; i++) tot2 += r2[i];
    float inv = rsqrtf(tot2 * (1.0f / 1024.0f) + 1e-5f);

    float4 wv = *(const float4*)(w + d);
    float4 bv = *(const float4*)(bias + d);
    uint2 o;
    o.x = packh2(a0 * inv * wv.x + bv.x, a1 * inv * wv.y + bv.y);
    o.y = packh2(a2 * inv * wv.z + bv.z, a3 * inv * wv.w + bv.w);
    *(uint2*)(g_xh + (size_t)bs * 1024 + d) = o;
}

// ---------------------------------------------------------------------------
// Projection, fp16 m16n8k16 + ldmatrix, 3-STAGE cp.async pipeline (prefetch
// distance 2 covers ~250cyc L2 latency; R13 ncu showed tensor=37%, latency-
// bound with 2 stages). CTA tile 128x64, 256 threads, k-chunk 32.
// Smem = 3*(128+64)*40*2 = 46080 B -> 4 CTAs/SM.
// ---------------------------------------------------------------------------
__global__ __launch_bounds__(256) void proj_mma_kernel(float* __restrict__ C)
{
    __shared__ __half As[3][128][40];
    __shared__ __half Bs[3][64][40];

    int m0 = blockIdx.x * 128, n0 = blockIdx.y * 64;
    int tid  = threadIdx.x;
    int warp = tid >> 5, lane = tid & 31;
    int g = lane >> 2, tg = lane & 3;

    const __half* ap = g_xh + (size_t)m0 * 1024;
    const __half* bp = g_wh + (size_t)n0 * 1024;

    float acc[8][4];
    #pragma unroll
    for (int i = 0; i < 8; i++)
        #pragma unroll
        for (int j = 0; j < 4; j++) acc[i][j] = 0.0f;

    auto stage = [&](int kc, int bb) {
        int k0 = kc * 32;
        {
            int r = tid >> 2, c = tid & 3;
            cp16(&As[bb][r][c * 8], ap + (size_t)r * 1024 + k0 + c * 8);
        }
        {
            int i = tid + 256, r = i >> 2, c = i & 3;
            cp16(&As[bb][r][c * 8], ap + (size_t)r * 1024 + k0 + c * 8);
        }
        {
            int r = tid >> 2, c = tid & 3;
            cp16(&Bs[bb][r][c * 8], bp + (size_t)r * 1024 + k0 + c * 8);
        }
        cp_commit();
    };

    stage(0, 0);
    stage(1, 1);
    for (int kc = 0; kc < 32; kc++) {
        int buf = kc % 3;
        if (kc < 30)      { stage(kc + 2, (kc + 2) % 3); cp_wait<2>(); }
        else if (kc == 30){ cp_wait<1>(); }
        else              { cp_wait<0>(); }
        __syncthreads();

        unsigned as_base = (unsigned)__cvta_generic_to_shared(&As[buf][0][0]);
        unsigned bs_base = (unsigned)__cvta_generic_to_shared(&Bs[buf][0][0]);

        #pragma unroll
        for (int kt = 0; kt < 2; kt++) {
            unsigned Af[4];
            {
                int t = lane >> 3;
                unsigned addr = as_base +
                    ((unsigned)((warp*16 + (t & 1)*8 + (lane & 7)) * 40
                                + kt*16 + (t >> 1)*8)) * 2;
                ldsm4(Af[0], Af[1], Af[2], Af[3], addr);
            }
            #pragma unroll
            for (int np = 0; np < 4; np++) {
                int t = lane >> 3;
                unsigned addr = bs_base +
                    ((unsigned)(((np*2 + (t >> 1))*8 + (lane & 7)) * 40
                                + kt*16 + (t & 1)*8)) * 2;
                unsigned r0, r1, r2, r3;
                ldsm4(r0, r1, r2, r3, addr);
                mma_f16(acc[np*2    ], Af, r0, r1);
                mma_f16(acc[np*2 + 1], Af, r2, r3);
            }
        }
        __syncthreads();
    }

    #pragma unroll
    for (int nt = 0; nt < 8; nt++) {
        float2 v0 = make_float2(acc[nt][0], acc[nt][1]);
        float2 v1 = make_float2(acc[nt][2], acc[nt][3]);
        *(float2*)(C + (size_t)(m0 + warp*16 + g    ) * 1024 + n0 + nt*8 + 2*tg) = v0;
        *(float2*)(C + (size_t)(m0 + warp*16 + g + 8) * 1024 + n0 + nt*8 + 2*tg) = v1;
    }
}

// ---------------------------------------------------------------------------
extern "C" void kernel_launch(void* const* d_in, const int* in_sizes, int n_in,
                              void* d_out, int out_size)
{
    const float* x_q    = (const float*)d_in[0];
    const float* x_k    = (const float*)d_in[1];
    const float* x_v    = (const float*)d_in[2];
    const float* qn_w   = (const float*)d_in[3];
    const float* qn_b   = (const float*)d_in[4];
    const float* kn_w   = (const float*)d_in[5];
    const float* kn_b   = (const float*)d_in[6];
    const float* n_w    = (const float*)d_in[7];
    const float* n_b    = (const float*)d_in[8];
    const float* proj_w = (const float*)d_in[9];
    float* out = (float*)d_out;

    // 0.125 * log2(e): softmax in log2 domain (single EX2 per score)
    const float qscale = 0.125f * 1.4426950408889634f;

    // fused prep: Q-LN (8192) + K-LN (512) + V fp16 (256) + W fp16 (1024)
    prep_kernel<<<9984, 256>>>(x_q, x_k, x_v, proj_w,
                               qn_w, qn_b, kn_w, kn_b, qscale);

    attn_mma_kernel<<<dim3(S_/128, B_*H_), 128>>>();

    lnD_kernel<<<B_*S_, 256>>>(n_w, n_b);

    proj_mma_kernel<<<dim3(B_*S_/128, D_/64), 256>>>(out);
}

// round 15
// speedup vs baseline: 1.4957x; 1.4957x over previous
#include <cuda_runtime.h>
#include <cuda_fp16.h>

#define B_  4
#define S_  2048
#define N_  2048
#define D_  1024
#define H_  16
#define HD_ 64

// Scratch (allocation-free rule: __device__ globals)
__device__ __half g_qh[B_*H_*S_*HD_];  // LN'd, scaled 0.125*log2e, fp16
__device__ __half g_kh[B_*N_*HD_];     // LN'd K, fp16
__device__ __half g_vh[B_*N_*HD_];     // V fp16 (natural layout)
__device__ __half g_wh[D_*D_];         // proj W, fp16
__device__ __half g_oh[B_*H_*S_*HD_];  // attention output (B,H,S,HD) fp16
__device__ __half g_xh[B_*S_*D_];      // transposed + LN'd, fp16

// ---------------------------------------------------------------------------
// helpers
// ---------------------------------------------------------------------------
__device__ __forceinline__ float ex2(float x) {
    float y;
    asm("ex2.approx.ftz.f32 %0, %1;" : "=f"(y) : "f"(x));
    return y;
}
__device__ __forceinline__ unsigned packh2(float lo, float hi) {
    __half2 h = __floats2half2_rn(lo, hi);
    return *(unsigned*)&h;
}
__device__ __forceinline__ void mma_f16(float* c, const unsigned* a,
                                        unsigned b0, unsigned b1) {
    asm volatile(
        "mma.sync.aligned.m16n8k16.row.col.f32.f16.f16.f32 "
        "{%0,%1,%2,%3}, {%4,%5,%6,%7}, {%8,%9}, {%0,%1,%2,%3};"
        : "+f"(c[0]), "+f"(c[1]), "+f"(c[2]), "+f"(c[3])
        : "r"(a[0]), "r"(a[1]), "r"(a[2]), "r"(a[3]), "r"(b0), "r"(b1));
}
__device__ __forceinline__ void ldsm4(unsigned& r0, unsigned& r1, unsigned& r2,
                                      unsigned& r3, unsigned addr) {
    asm volatile("ldmatrix.sync.aligned.m8n8.x4.shared.b16 {%0,%1,%2,%3}, [%4];"
                 : "=r"(r0), "=r"(r1), "=r"(r2), "=r"(r3) : "r"(addr));
}
__device__ __forceinline__ void ldsm4t(unsigned& r0, unsigned& r1, unsigned& r2,
                                       unsigned& r3, unsigned addr) {
    asm volatile("ldmatrix.sync.aligned.m8n8.x4.trans.shared.b16 {%0,%1,%2,%3}, [%4];"
                 : "=r"(r0), "=r"(r1), "=r"(r2), "=r"(r3) : "r"(addr));
}
__device__ __forceinline__ void cp16(void* dst, const void* src) {
    unsigned d = (unsigned)__cvta_generic_to_shared(dst);
    asm volatile("cp.async.cg.shared.global [%0], [%1], 16;" :: "r"(d), "l"(src));
}
__device__ __forceinline__ void cp_commit() {
    asm volatile("cp.async.commit_group;");
}
template<int NN> __device__ __forceinline__ void cp_wait() {
    asm volatile("cp.async.wait_group %0;" :: "n"(NN));
}

// ---------------------------------------------------------------------------
// LayerNorm over rows of 64: 16 lanes per row (float4/lane), 2 rows per warp,
// 16 rows per 256-thread CTA. Fully 16B-coalesced. Writes fp16.
// ---------------------------------------------------------------------------
__global__ __launch_bounds__(256) void ln64_kernel(
    const float* __restrict__ x, const float* __restrict__ w,
    const float* __restrict__ bias, float scale, int nrows, int which)
{
    int row = blockIdx.x * 16 + (threadIdx.x >> 4);
    if (row >= nrows) return;
    int l16 = threadIdx.x & 15;
    float4 v = ((const float4*)(x + (size_t)row * 64))[l16];
    float s = v.x + v.y + v.z + v.w;
    #pragma unroll
    for (int m = 8; m; m >>= 1) s += __shfl_xor_sync(0xffffffffu, s, m);
    float mean = s * (1.0f / 64.0f);
    float a0 = v.x - mean, a1 = v.y - mean, a2 = v.z - mean, a3 = v.w - mean;
    float q2 = a0*a0 + a1*a1 + a2*a2 + a3*a3;
    #pragma unroll
    for (int m = 8; m; m >>= 1) q2 += __shfl_xor_sync(0xffffffffu, q2, m);
    float inv = rsqrtf(q2 * (1.0f / 64.0f) + 1e-5f);
    float4 wv = ((const float4*)w)[l16];
    float4 bv = ((const float4*)bias)[l16];
    uint2 o;
    o.x = packh2((a0 * inv * wv.x + bv.x) * scale, (a1 * inv * wv.y + bv.y) * scale);
    o.y = packh2((a2 * inv * wv.z + bv.z) * scale, (a3 * inv * wv.w + bv.w) * scale);
    __half* dst = which ? g_kh : g_qh;
    ((uint2*)(dst + (size_t)row * 64))[l16] = o;
}

// ---------------------------------------------------------------------------
// f32 -> fp16 convert. which==0 -> g_vh, which==1 -> g_wh
// ---------------------------------------------------------------------------
__global__ __launch_bounds__(256) void tohalf_kernel(
    const float* __restrict__ src, int n4, int which)
{
    __half* dst = which ? g_wh : g_vh;
    for (int i4 = blockIdx.x * 256 + threadIdx.x; i4 < n4; i4 += gridDim.x * 256) {
        float4 t = ((const float4*)src)[i4];
        uint2 o;
        o.x = packh2(t.x, t.y);
        o.y = packh2(t.z, t.w);
        ((uint2*)dst)[i4] = o;
    }
}

// ---------------------------------------------------------------------------
// Flash attention (R12 measured-best): fp16 m16n8k16, 32 queries/warp,
// 4 warps / 128 threads, minBlocks=3, grid (S/128, B*H).
// Smem = 2 * 64*72*2 * 2 = 36864 B. fp16 output.
// ---------------------------------------------------------------------------
__global__ __launch_bounds__(128, 3) void attn_mma_kernel()
{
    __shared__ __half Ks[2][64][72];
    __shared__ __half Vs[2][64][72];

    int bh = blockIdx.y;
    int b  = bh >> 4;
    int tid  = threadIdx.x;
    int warp = tid >> 5, lane = tid & 31;
    int g = lane >> 2, tg = lane & 3;

    const __half* kp = g_kh + (size_t)b * N_ * 64;
    const __half* vp = g_vh + (size_t)b * N_ * 64;

    const __half* qp = g_qh + ((size_t)bh * S_ + blockIdx.x * 128 + warp * 32) * 64;
    unsigned Qf[2][4][4];
    #pragma unroll
    for (int m = 0; m < 2; m++) {
        #pragma unroll
        for (int kt = 0; kt < 4; kt++) {
            Qf[m][kt][0] = *(const unsigned*)(qp + (size_t)(m*16 + g     ) * 64 + kt*16 + 2*tg);
            Qf[m][kt][1] = *(const unsigned*)(qp + (size_t)(m*16 + g + 8 ) * 64 + kt*16 + 2*tg);
            Qf[m][kt][2] = *(const unsigned*)(qp + (size_t)(m*16 + g     ) * 64 + kt*16 + 8 + 2*tg);
            Qf[m][kt][3] = *(const unsigned*)(qp + (size_t)(m*16 + g + 8 ) * 64 + kt*16 + 8 + 2*tg);
        }
    }

    float Oa[2][8][4];
    #pragma unroll
    for (int m = 0; m < 2; m++)
        #pragma unroll
        for (int i = 0; i < 8; i++)
            #pragma unroll
            for (int j = 0; j < 4; j++) Oa[m][i][j] = 0.0f;
    float La[2][4];
    #pragma unroll
    for (int m = 0; m < 2; m++)
        #pragma unroll
        for (int j = 0; j < 4; j++) La[m][j] = 0.0f;
    const unsigned ones_b = (g == 0) ? 0x3C003C00u : 0u;  // B[0][k]=1, else 0

    auto stage = [&](int kc, int bb) {
        #pragma unroll
        for (int j = 0; j < 8; j++) {
            int i = tid + 128 * j;           // 0..1023
            if (i < 512) {
                int r = i >> 3, c = i & 7;
                cp16(&Ks[bb][r][c * 8], kp + ((size_t)kc * 64 + r) * 64 + c * 8);
            } else {
                int i2 = i - 512;
                int r = i2 >> 3, c = i2 & 7;
                cp16(&Vs[bb][r][c * 8], vp + ((size_t)kc * 64 + r) * 64 + c * 8);
            }
        }
        cp_commit();
    };

    stage(0, 0);
    int buf = 0;
    for (int kc = 0; kc < N_ / 64; kc++) {
        if (kc < N_ / 64 - 1) { stage(kc + 1, buf ^ 1); cp_wait<1>(); }
        else                  { cp_wait<0>(); }
        __syncthreads();

        unsigned ks_base = (unsigned)__cvta_generic_to_shared(&Ks[buf][0][0]);
        unsigned vs_base = (unsigned)__cvta_generic_to_shared(&Vs[buf][0][0]);

        unsigned Pf[2][4][4];
        #pragma unroll
        for (int ntp = 0; ntp < 4; ntp++) {
            float sc[2][2][4];
            #pragma unroll
            for (int sub = 0; sub < 2; sub++) {
                int nt = ntp * 2 + sub;
                #pragma unroll
                for (int m = 0; m < 2; m++)
                    sc[m][sub][0] = sc[m][sub][1] = sc[m][sub][2] = sc[m][sub][3] = 0.0f;
                unsigned a0 = ks_base +
                    ((unsigned)((nt*8 + (lane & 7)) * 72 + (lane >> 3) * 8)) * 2;
                unsigned r0, r1, r2, r3;
                ldsm4(r0, r1, r2, r3, a0);            // kt0, kt1
                #pragma unroll
                for (int m = 0; m < 2; m++) {
                    mma_f16(sc[m][sub], Qf[m][0], r0, r1);
                    mma_f16(sc[m][sub], Qf[m][1], r2, r3);
                }
                ldsm4(r0, r1, r2, r3, a0 + 64);       // kt2, kt3
                #pragma unroll
                for (int m = 0; m < 2; m++) {
                    mma_f16(sc[m][sub], Qf[m][2], r0, r1);
                    mma_f16(sc[m][sub], Qf[m][3], r2, r3);
                }
            }
            #pragma unroll
            for (int m = 0; m < 2; m++) {
                #pragma unroll
                for (int sub = 0; sub < 2; sub++) {
                    sc[m][sub][0] = ex2(sc[m][sub][0]);
                    sc[m][sub][1] = ex2(sc[m][sub][1]);
                    sc[m][sub][2] = ex2(sc[m][sub][2]);
                    sc[m][sub][3] = ex2(sc[m][sub][3]);
                }
                Pf[m][ntp][0] = packh2(sc[m][0][0], sc[m][0][1]);
                Pf[m][ntp][1] = packh2(sc[m][0][2], sc[m][0][3]);
                Pf[m][ntp][2] = packh2(sc[m][1][0], sc[m][1][1]);
                Pf[m][ntp][3] = packh2(sc[m][1][2], sc[m][1][3]);
            }
        }

        #pragma unroll
        for (int m = 0; m < 2; m++)
            #pragma unroll
            for (int kt = 0; kt < 4; kt++)
                mma_f16(La[m], Pf[m][kt], ones_b, ones_b);

        #pragma unroll
        for (int nt = 0; nt < 8; nt++) {
            unsigned a0 = vs_base +
                ((unsigned)(((lane >> 3) * 8 + (lane & 7)) * 72 + nt * 8)) * 2;
            unsigned r0, r1, r2, r3;
            ldsm4t(r0, r1, r2, r3, a0);                    // keys 0..31
            #pragma unroll
            for (int m = 0; m < 2; m++) {
                mma_f16(Oa[m][nt], Pf[m][0], r0, r1);
                mma_f16(Oa[m][nt], Pf[m][1], r2, r3);
            }
            ldsm4t(r0, r1, r2, r3, a0 + 32 * 72 * 2);      // keys 32..63
            #pragma unroll
            for (int m = 0; m < 2; m++) {
                mma_f16(Oa[m][nt], Pf[m][2], r0, r1);
                mma_f16(Oa[m][nt], Pf[m][3], r2, r3);
            }
        }
        __syncthreads();
        buf ^= 1;
    }

    __half* op = g_oh + ((size_t)bh * S_ + blockIdx.x * 128 + warp * 32) * 64;
    #pragma unroll
    for (int m = 0; m < 2; m++) {
        float li0 = __shfl_sync(0xffffffffu, La[m][0], lane & ~3);
        float li1 = __shfl_sync(0xffffffffu, La[m][2], lane & ~3);
        float inv0 = 1.0f / li0, inv1 = 1.0f / li1;
        #pragma unroll
        for (int nt = 0; nt < 8; nt++) {
            unsigned v0 = packh2(Oa[m][nt][0] * inv0, Oa[m][nt][1] * inv0);
            unsigned v1 = packh2(Oa[m][nt][2] * inv1, Oa[m][nt][3] * inv1);
            *(unsigned*)(op + (size_t)(m*16 + g     ) * 64 + nt*8 + 2*tg) = v0;
            *(unsigned*)(op + (size_t)(m*16 + g + 8 ) * 64 + nt*8 + 2*tg) = v1;
        }
    }
}

// ---------------------------------------------------------------------------
// Gather fp16 (B,H,S,HD) -> (B,S,D) + LayerNorm over D=1024 -> fp16 output.
// ---------------------------------------------------------------------------
__global__ __launch_bounds__(256) void lnD_kernel(
    const float* __restrict__ w, const float* __restrict__ bias)
{
    int bs = blockIdx.x;
    int b = bs >> 11, s = bs & 2047;
    int tid = threadIdx.x;
    int d = tid * 4;
    int h = d >> 6, hd = d & 63;
    uint2 raw = *(const uint2*)(g_oh + (((size_t)(b * H_ + h) * S_ + s) * 64 + hd));
    float2 p0 = __half22float2(*(__half2*)&raw.x);
    float2 p1 = __half22float2(*(__half2*)&raw.y);
    float v0 = p0.x, v1 = p0.y, v2 = p1.x, v3 = p1.y;

    __shared__ float r1[8], r2[8];
    float sum = v0 + v1 + v2 + v3;
    #pragma unroll
    for (int m = 16; m; m >>= 1) sum += __shfl_xor_sync(0xffffffffu, sum, m);
    if ((tid & 31) == 0) r1[tid >> 5] = sum;
    __syncthreads();
    float tot = 0.0f;
    #pragma unroll
    for (int i = 0; i < 8; i++) tot += r1[i];
    float mean = tot * (1.0f / 1024.0f);

    float a0 = v0 - mean, a1 = v1 - mean, a2 = v2 - mean, a3 = v3 - mean;
    float sq = a0*a0 + a1*a1 + a2*a2 + a3*a3;
    #pragma unroll
    for (int m = 16; m; m >>= 1) sq += __shfl_xor_sync(0xffffffffu, sq, m);
    if ((tid & 31) == 0) r2[tid >> 5] = sq;
    __syncthreads();
    float tot2 = 0.0f;
    #pragma unroll
    for (int i = 0; i < 8; i++) tot2 += r2[i];
    float inv = rsqrtf(tot2 * (1.0f / 1024.0f) + 1e-5f);

    float4 wv = *(const float4*)(w + d);
    float4 bv = *(const float4*)(bias + d);
    uint2 o;
    o.x = packh2(a0 * inv * wv.x + bv.x, a1 * inv * wv.y + bv.y);
    o.y = packh2(a2 * inv * wv.z + bv.z, a3 * inv * wv.w + bv.w);
    *(uint2*)(g_xh + (size_t)bs * 1024 + d) = o;
}

// ---------------------------------------------------------------------------
// Projection, fp16 m16n8k16 + ldmatrix, 3-stage cp.async pipeline with
// COMPILE-TIME-CONSTANT buffer slots (R14's runtime `%3` indexing exploded
// IMAD/ALU work; here the k-loop runs in groups of 3 unrolled bodies with
// literal buffer indices, so all smem addresses fold to base+immediate).
// CTA tile 128x64, 256 threads, k-chunk 32. Smem = 3*(128+64)*40*2 = 46080 B.
// ---------------------------------------------------------------------------
__global__ __launch_bounds__(256) void proj_mma_kernel(float* __restrict__ C)
{
    __shared__ __half As[3][128][40];
    __shared__ __half Bs[3][64][40];

    int m0 = blockIdx.x * 128, n0 = blockIdx.y * 64;
    int tid  = threadIdx.x;
    int warp = tid >> 5, lane = tid & 31;
    int g = lane >> 2, tg = lane & 3;

    const __half* ap = g_xh + (size_t)m0 * 1024;
    const __half* bp = g_wh + (size_t)n0 * 1024;

    float acc[8][4];
    #pragma unroll
    for (int i = 0; i < 8; i++)
        #pragma unroll
        for (int j = 0; j < 4; j++) acc[i][j] = 0.0f;

    // hoisted per-thread staging coordinates
    int sr0 = tid >> 2,          sc0 = (tid & 3) * 8;        // A rows 0..63
    int sr1 = (tid + 256) >> 2,  sc1 = ((tid + 256) & 3) * 8; // A rows 64..127

    auto stage = [&](int kc, int bb) {
        int k0 = kc * 32;
        cp16(&As[bb][sr0][sc0], ap + (size_t)sr0 * 1024 + k0 + sc0);
        cp16(&As[bb][sr1][sc1], ap + (size_t)sr1 * 1024 + k0 + sc1);
        cp16(&Bs[bb][sr0][sc0], bp + (size_t)sr0 * 1024 + k0 + sc0);
        cp_commit();
    };

    // hoisted fragment address offsets (within a buffer)
    int t = lane >> 3;
    unsigned a_off = ((unsigned)((warp*16 + (t & 1)*8 + (lane & 7)) * 40
                                 + (t >> 1)*8)) * 2;
    unsigned b_off[4];
    #pragma unroll
    for (int np = 0; np < 4; np++)
        b_off[np] = ((unsigned)(((np*2 + (t >> 1))*8 + (lane & 7)) * 40
                                + (t & 1)*8)) * 2;

    unsigned asb[3], bsb[3];
    #pragma unroll
    for (int bb = 0; bb < 3; bb++) {
        asb[bb] = (unsigned)__cvta_generic_to_shared(&As[bb][0][0]);
        bsb[bb] = (unsigned)__cvta_generic_to_shared(&Bs[bb][0][0]);
    }

    auto compute = [&](unsigned as_base, unsigned bs_base) {
        #pragma unroll
        for (int kt = 0; kt < 2; kt++) {
            unsigned Af[4];
            ldsm4(Af[0], Af[1], Af[2], Af[3], as_base + a_off + kt*32);
            #pragma unroll
            for (int np = 0; np < 4; np++) {
                unsigned r0, r1, r2, r3;
                ldsm4(r0, r1, r2, r3, bs_base + b_off[np] + kt*32);
                mma_f16(acc[np*2    ], Af, r0, r1);
                mma_f16(acc[np*2 + 1], Af, r2, r3);
            }
        }
    };

    stage(0, 0);
    stage(1, 1);
    for (int grp = 0; grp < 10; grp++) {
        int kc = grp * 3;
        // body kc+0: consume buf0, prefetch kc+2 -> buf2
        stage(kc + 2, 2);
        cp_wait<2>();
        __syncthreads();
        compute(asb[0], bsb[0]);
        __syncthreads();
        // body kc+1: consume buf1, prefetch kc+3 -> buf0
        stage(kc + 3, 0);
        cp_wait<2>();
        __syncthreads();
        compute(asb[1], bsb[1]);
        __syncthreads();
        // body kc+2: consume buf2, prefetch kc+4 -> buf1
        stage(kc + 4, 1);
        cp_wait<2>();
        __syncthreads();
        compute(asb[2], bsb[2]);
        __syncthreads();
    }
    // tail: kc=30 (buf0), kc=31 (buf1); stages 30,31 already issued in grp 9
    cp_wait<1>();
    __syncthreads();
    compute(asb[0], bsb[0]);
    __syncthreads();
    cp_wait<0>();
    __syncthreads();
    compute(asb[1], bsb[1]);

    #pragma unroll
    for (int nt = 0; nt < 8; nt++) {
        float2 v0 = make_float2(acc[nt][0], acc[nt][1]);
        float2 v1 = make_float2(acc[nt][2], acc[nt][3]);
        *(float2*)(C + (size_t)(m0 + warp*16 + g    ) * 1024 + n0 + nt*8 + 2*tg) = v0;
        *(float2*)(C + (size_t)(m0 + warp*16 + g + 8) * 1024 + n0 + nt*8 + 2*tg) = v1;
    }
}

// ---------------------------------------------------------------------------
extern "C" void kernel_launch(void* const* d_in, const int* in_sizes, int n_in,
                              void* d_out, int out_size)
{
    const float* x_q    = (const float*)d_in[0];
    const float* x_k    = (const float*)d_in[1];
    const float* x_v    = (const float*)d_in[2];
    const float* qn_w   = (const float*)d_in[3];
    const float* qn_b   = (const float*)d_in[4];
    const float* kn_w   = (const float*)d_in[5];
    const float* kn_b   = (const float*)d_in[6];
    const float* n_w    = (const float*)d_in[7];
    const float* n_b    = (const float*)d_in[8];
    const float* proj_w = (const float*)d_in[9];
    float* out = (float*)d_out;

    // 0.125 * log2(e): softmax in log2 domain (single EX2 per score)
    const float qscale = 0.125f * 1.4426950408889634f;

    ln64_kernel<<<(B_*H_*S_) / 16, 256>>>(x_q, qn_w, qn_b, qscale, B_*H_*S_, 0);
    ln64_kernel<<<(B_*N_) / 16, 256>>>(x_k, kn_w, kn_b, 1.0f, B_*N_, 1);
    tohalf_kernel<<<256, 256>>>(x_v, B_*N_*HD_/4, 0);
    tohalf_kernel<<<1024, 256>>>(proj_w, D_*D_/4, 1);

    attn_mma_kernel<<<dim3(S_/128, B_*H_), 128>>>();

    lnD_kernel<<<B_*S_, 256>>>(n_w, n_b);

    proj_mma_kernel<<<dim3(B_*S_/128, D_/64), 256>>>(out);
}

// round 16
// speedup vs baseline: 1.5044x; 1.0058x over previous
#include <cuda_runtime.h>
#include <cuda_fp16.h>

#define B_  4
#define S_  2048
#define N_  2048
#define D_  1024
#define H_  16
#define HD_ 64

// Scratch (allocation-free rule: __device__ globals)
__device__ __half g_qh[B_*H_*S_*HD_];  // LN'd, scaled 0.125*log2e, fp16
__device__ __half g_kh[B_*N_*HD_];     // LN'd K, fp16
__device__ __half g_vh[B_*N_*HD_];     // V fp16 (natural layout)
__device__ __half g_wh[D_*D_];         // proj W, fp16
__device__ __half g_oh[B_*H_*S_*HD_];  // attention output (B,H,S,HD) fp16
__device__ __half g_xh[B_*S_*D_];      // transposed + LN'd, fp16

// ---------------------------------------------------------------------------
// helpers
// ---------------------------------------------------------------------------
__device__ __forceinline__ float ex2(float x) {
    float y;
    asm("ex2.approx.ftz.f32 %0, %1;" : "=f"(y) : "f"(x));
    return y;
}
__device__ __forceinline__ unsigned packh2(float lo, float hi) {
    __half2 h = __floats2half2_rn(lo, hi);
    return *(unsigned*)&h;
}
__device__ __forceinline__ void mma_f16(float* c, const unsigned* a,
                                        unsigned b0, unsigned b1) {
    asm volatile(
        "mma.sync.aligned.m16n8k16.row.col.f32.f16.f16.f32 "
        "{%0,%1,%2,%3}, {%4,%5,%6,%7}, {%8,%9}, {%0,%1,%2,%3};"
        : "+f"(c[0]), "+f"(c[1]), "+f"(c[2]), "+f"(c[3])
        : "r"(a[0]), "r"(a[1]), "r"(a[2]), "r"(a[3]), "r"(b0), "r"(b1));
}
__device__ __forceinline__ void ldsm4(unsigned& r0, unsigned& r1, unsigned& r2,
                                      unsigned& r3, unsigned addr) {
    asm volatile("ldmatrix.sync.aligned.m8n8.x4.shared.b16 {%0,%1,%2,%3}, [%4];"
                 : "=r"(r0), "=r"(r1), "=r"(r2), "=r"(r3) : "r"(addr));
}
__device__ __forceinline__ void ldsm4t(unsigned& r0, unsigned& r1, unsigned& r2,
                                       unsigned& r3, unsigned addr) {
    asm volatile("ldmatrix.sync.aligned.m8n8.x4.trans.shared.b16 {%0,%1,%2,%3}, [%4];"
                 : "=r"(r0), "=r"(r1), "=r"(r2), "=r"(r3) : "r"(addr));
}
__device__ __forceinline__ void cp16(void* dst, const void* src) {
    unsigned d = (unsigned)__cvta_generic_to_shared(dst);
    asm volatile("cp.async.cg.shared.global [%0], [%1], 16;" :: "r"(d), "l"(src));
}
__device__ __forceinline__ void cp_commit() {
    asm volatile("cp.async.commit_group;");
}
template<int NN> __device__ __forceinline__ void cp_wait() {
    asm volatile("cp.async.wait_group %0;" :: "n"(NN));
}

// ---------------------------------------------------------------------------
// LayerNorm over rows of 64: 16 lanes per row (float4/lane), 2 rows per warp,
// 16 rows per 256-thread CTA. Fully 16B-coalesced. Writes fp16.
// ---------------------------------------------------------------------------
__global__ __launch_bounds__(256) void ln64_kernel(
    const float* __restrict__ x, const float* __restrict__ w,
    const float* __restrict__ bias, float scale, int nrows, int which)
{
    int row = blockIdx.x * 16 + (threadIdx.x >> 4);
    if (row >= nrows) return;
    int l16 = threadIdx.x & 15;
    float4 v = ((const float4*)(x + (size_t)row * 64))[l16];
    float s = v.x + v.y + v.z + v.w;
    #pragma unroll
    for (int m = 8; m; m >>= 1) s += __shfl_xor_sync(0xffffffffu, s, m);
    float mean = s * (1.0f / 64.0f);
    float a0 = v.x - mean, a1 = v.y - mean, a2 = v.z - mean, a3 = v.w - mean;
    float q2 = a0*a0 + a1*a1 + a2*a2 + a3*a3;
    #pragma unroll
    for (int m = 8; m; m >>= 1) q2 += __shfl_xor_sync(0xffffffffu, q2, m);
    float inv = rsqrtf(q2 * (1.0f / 64.0f) + 1e-5f);
    float4 wv = ((const float4*)w)[l16];
    float4 bv = ((const float4*)bias)[l16];
    uint2 o;
    o.x = packh2((a0 * inv * wv.x + bv.x) * scale, (a1 * inv * wv.y + bv.y) * scale);
    o.y = packh2((a2 * inv * wv.z + bv.z) * scale, (a3 * inv * wv.w + bv.w) * scale);
    __half* dst = which ? g_kh : g_qh;
    ((uint2*)(dst + (size_t)row * 64))[l16] = o;
}

// ---------------------------------------------------------------------------
// f32 -> fp16 convert. which==0 -> g_vh, which==1 -> g_wh
// ---------------------------------------------------------------------------
__global__ __launch_bounds__(256) void tohalf_kernel(
    const float* __restrict__ src, int n4, int which)
{
    __half* dst = which ? g_wh : g_vh;
    for (int i4 = blockIdx.x * 256 + threadIdx.x; i4 < n4; i4 += gridDim.x * 256) {
        float4 t = ((const float4*)src)[i4];
        uint2 o;
        o.x = packh2(t.x, t.y);
        o.y = packh2(t.z, t.w);
        ((uint2*)dst)[i4] = o;
    }
}

// ---------------------------------------------------------------------------
// Flash attention: fp16 m16n8k16, 32 queries/warp, 4 warps / 128 threads,
// minBlocks=3, grid (S/128, B*H). Rowsum accumulated on the (idle) FMA pipe
// in registers (linear, so the quad reduction happens ONCE in the epilogue) —
// frees the 8 ones-column MMAs per chunk from the bottleneck tensor pipe.
// Smem = 2 * 64*72*2 * 2 = 36864 B. fp16 output.
// ---------------------------------------------------------------------------
__global__ __launch_bounds__(128, 3) void attn_mma_kernel()
{
    __shared__ __half Ks[2][64][72];
    __shared__ __half Vs[2][64][72];

    int bh = blockIdx.y;
    int b  = bh >> 4;
    int tid  = threadIdx.x;
    int warp = tid >> 5, lane = tid & 31;
    int g = lane >> 2, tg = lane & 3;

    const __half* kp = g_kh + (size_t)b * N_ * 64;
    const __half* vp = g_vh + (size_t)b * N_ * 64;

    const __half* qp = g_qh + ((size_t)bh * S_ + blockIdx.x * 128 + warp * 32) * 64;
    unsigned Qf[2][4][4];
    #pragma unroll
    for (int m = 0; m < 2; m++) {
        #pragma unroll
        for (int kt = 0; kt < 4; kt++) {
            Qf[m][kt][0] = *(const unsigned*)(qp + (size_t)(m*16 + g     ) * 64 + kt*16 + 2*tg);
            Qf[m][kt][1] = *(const unsigned*)(qp + (size_t)(m*16 + g + 8 ) * 64 + kt*16 + 2*tg);
            Qf[m][kt][2] = *(const unsigned*)(qp + (size_t)(m*16 + g     ) * 64 + kt*16 + 8 + 2*tg);
            Qf[m][kt][3] = *(const unsigned*)(qp + (size_t)(m*16 + g + 8 ) * 64 + kt*16 + 8 + 2*tg);
        }
    }

    float Oa[2][8][4];
    #pragma unroll
    for (int m = 0; m < 2; m++)
        #pragma unroll
        for (int i = 0; i < 8; i++)
            #pragma unroll
            for (int j = 0; j < 4; j++) Oa[m][i][j] = 0.0f;
    float rs[2][2] = {{0.0f, 0.0f}, {0.0f, 0.0f}};  // rowsums: [m][row g / g+8]

    auto stage = [&](int kc, int bb) {
        #pragma unroll
        for (int j = 0; j < 8; j++) {
            int i = tid + 128 * j;           // 0..1023
            if (i < 512) {
                int r = i >> 3, c = i & 7;
                cp16(&Ks[bb][r][c * 8], kp + ((size_t)kc * 64 + r) * 64 + c * 8);
            } else {
                int i2 = i - 512;
                int r = i2 >> 3, c = i2 & 7;
                cp16(&Vs[bb][r][c * 8], vp + ((size_t)kc * 64 + r) * 64 + c * 8);
            }
        }
        cp_commit();
    };

    stage(0, 0);
    int buf = 0;
    for (int kc = 0; kc < N_ / 64; kc++) {
        if (kc < N_ / 64 - 1) { stage(kc + 1, buf ^ 1); cp_wait<1>(); }
        else                  { cp_wait<0>(); }
        __syncthreads();

        unsigned ks_base = (unsigned)__cvta_generic_to_shared(&Ks[buf][0][0]);
        unsigned vs_base = (unsigned)__cvta_generic_to_shared(&Vs[buf][0][0]);

        unsigned Pf[2][4][4];
        #pragma unroll
        for (int ntp = 0; ntp < 4; ntp++) {
            float sc[2][2][4];
            #pragma unroll
            for (int sub = 0; sub < 2; sub++) {
                int nt = ntp * 2 + sub;
                #pragma unroll
                for (int m = 0; m < 2; m++)
                    sc[m][sub][0] = sc[m][sub][1] = sc[m][sub][2] = sc[m][sub][3] = 0.0f;
                unsigned a0 = ks_base +
                    ((unsigned)((nt*8 + (lane & 7)) * 72 + (lane >> 3) * 8)) * 2;
                unsigned r0, r1, r2, r3;
                ldsm4(r0, r1, r2, r3, a0);            // kt0, kt1
                #pragma unroll
                for (int m = 0; m < 2; m++) {
                    mma_f16(sc[m][sub], Qf[m][0], r0, r1);
                    mma_f16(sc[m][sub], Qf[m][1], r2, r3);
                }
                ldsm4(r0, r1, r2, r3, a0 + 64);       // kt2, kt3
                #pragma unroll
                for (int m = 0; m < 2; m++) {
                    mma_f16(sc[m][sub], Qf[m][2], r0, r1);
                    mma_f16(sc[m][sub], Qf[m][3], r2, r3);
                }
            }
            #pragma unroll
            for (int m = 0; m < 2; m++) {
                #pragma unroll
                for (int sub = 0; sub < 2; sub++) {
                    sc[m][sub][0] = ex2(sc[m][sub][0]);
                    sc[m][sub][1] = ex2(sc[m][sub][1]);
                    sc[m][sub][2] = ex2(sc[m][sub][2]);
                    sc[m][sub][3] = ex2(sc[m][sub][3]);
                }
                // rowsum on FMA pipe (row g: c0,c1; row g+8: c2,c3)
                rs[m][0] += (sc[m][0][0] + sc[m][0][1]) + (sc[m][1][0] + sc[m][1][1]);
                rs[m][1] += (sc[m][0][2] + sc[m][0][3]) + (sc[m][1][2] + sc[m][1][3]);
                Pf[m][ntp][0] = packh2(sc[m][0][0], sc[m][0][1]);
                Pf[m][ntp][1] = packh2(sc[m][0][2], sc[m][0][3]);
                Pf[m][ntp][2] = packh2(sc[m][1][0], sc[m][1][1]);
                Pf[m][ntp][3] = packh2(sc[m][1][2], sc[m][1][3]);
            }
        }

        #pragma unroll
        for (int nt = 0; nt < 8; nt++) {
            unsigned a0 = vs_base +
                ((unsigned)(((lane >> 3) * 8 + (lane & 7)) * 72 + nt * 8)) * 2;
            unsigned r0, r1, r2, r3;
            ldsm4t(r0, r1, r2, r3, a0);                    // keys 0..31
            #pragma unroll
            for (int m = 0; m < 2; m++) {
                mma_f16(Oa[m][nt], Pf[m][0], r0, r1);
                mma_f16(Oa[m][nt], Pf[m][1], r2, r3);
            }
            ldsm4t(r0, r1, r2, r3, a0 + 32 * 72 * 2);      // keys 32..63
            #pragma unroll
            for (int m = 0; m < 2; m++) {
                mma_f16(Oa[m][nt], Pf[m][2], r0, r1);
                mma_f16(Oa[m][nt], Pf[m][3], r2, r3);
            }
        }
        __syncthreads();
        buf ^= 1;
    }

    // epilogue: quad-reduce rowsums once; normalize; fp16 store
    __half* op = g_oh + ((size_t)bh * S_ + blockIdx.x * 128 + warp * 32) * 64;
    #pragma unroll
    for (int m = 0; m < 2; m++) {
        float s0 = rs[m][0], s1 = rs[m][1];
        s0 += __shfl_xor_sync(0xffffffffu, s0, 1);
        s0 += __shfl_xor_sync(0xffffffffu, s0, 2);
        s1 += __shfl_xor_sync(0xffffffffu, s1, 1);
        s1 += __shfl_xor_sync(0xffffffffu, s1, 2);
        float inv0 = 1.0f / s0, inv1 = 1.0f / s1;
        #pragma unroll
        for (int nt = 0; nt < 8; nt++) {
            unsigned v0 = packh2(Oa[m][nt][0] * inv0, Oa[m][nt][1] * inv0);
            unsigned v1 = packh2(Oa[m][nt][2] * inv1, Oa[m][nt][3] * inv1);
            *(unsigned*)(op + (size_t)(m*16 + g     ) * 64 + nt*8 + 2*tg) = v0;
            *(unsigned*)(op + (size_t)(m*16 + g + 8 ) * 64 + nt*8 + 2*tg) = v1;
        }
    }
}

// ---------------------------------------------------------------------------
// Gather fp16 (B,H,S,HD) -> (B,S,D) + LayerNorm over D=1024 -> fp16 output.
// ---------------------------------------------------------------------------
__global__ __launch_bounds__(256) void lnD_kernel(
    const float* __restrict__ w, const float* __restrict__ bias)
{
    int bs = blockIdx.x;
    int b = bs >> 11, s = bs & 2047;
    int tid = threadIdx.x;
    int d = tid * 4;
    int h = d >> 6, hd = d & 63;
    uint2 raw = *(const uint2*)(g_oh + (((size_t)(b * H_ + h) * S_ + s) * 64 + hd));
    float2 p0 = __half22float2(*(__half2*)&raw.x);
    float2 p1 = __half22float2(*(__half2*)&raw.y);
    float v0 = p0.x, v1 = p0.y, v2 = p1.x, v3 = p1.y;

    __shared__ float r1[8], r2[8];
    float sum = v0 + v1 + v2 + v3;
    #pragma unroll
    for (int m = 16; m; m >>= 1) sum += __shfl_xor_sync(0xffffffffu, sum, m);
    if ((tid & 31) == 0) r1[tid >> 5] = sum;
    __syncthreads();
    float tot = 0.0f;
    #pragma unroll
    for (int i = 0; i < 8; i++) tot += r1[i];
    float mean = tot * (1.0f / 1024.0f);

    float a0 = v0 - mean, a1 = v1 - mean, a2 = v2 - mean, a3 = v3 - mean;
    float sq = a0*a0 + a1*a1 + a2*a2 + a3*a3;
    #pragma unroll
    for (int m = 16; m; m >>= 1) sq += __shfl_xor_sync(0xffffffffu, sq, m);
    if ((tid & 31) == 0) r2[tid >> 5] = sq;
    __syncthreads();
    float tot2 = 0.0f;
    #pragma unroll
    for (int i = 0; i < 8; i++) tot2 += r2[i];
    float inv = rsqrtf(tot2 * (1.0f / 1024.0f) + 1e-5f);

    float4 wv = *(const float4*)(w + d);
    float4 bv = *(const float4*)(bias + d);
    uint2 o;
    o.x = packh2(a0 * inv * wv.x + bv.x, a1 * inv * wv.y + bv.y);
    o.y = packh2(a2 * inv * wv.z + bv.z, a3 * inv * wv.w + bv.w);
    *(uint2*)(g_xh + (size_t)bs * 1024 + d) = o;
}

// ---------------------------------------------------------------------------
// Projection: fp16 m16n8k16 + ldmatrix, 3-stage const-slot cp.async pipeline,
// SINGLE __syncthreads per body (wait<1> -> sync -> restage -> compute; the
// one barrier proves both "stage kc landed everywhere" and "compute kc-1 done
// everywhere", making the restage safe). CTA tile 128x64, 256 threads,
// k-chunk 32. Smem = 3*(128+64)*40*2 = 46080 B.
// ---------------------------------------------------------------------------
__global__ __launch_bounds__(256) void proj_mma_kernel(float* __restrict__ C)
{
    __shared__ __half As[3][128][40];
    __shared__ __half Bs[3][64][40];

    int m0 = blockIdx.x * 128, n0 = blockIdx.y * 64;
    int tid  = threadIdx.x;
    int warp = tid >> 5, lane = tid & 31;
    int g = lane >> 2, tg = lane & 3;

    const __half* ap = g_xh + (size_t)m0 * 1024;
    const __half* bp = g_wh + (size_t)n0 * 1024;

    float acc[8][4];
    #pragma unroll
    for (int i = 0; i < 8; i++)
        #pragma unroll
        for (int j = 0; j < 4; j++) acc[i][j] = 0.0f;

    int sr0 = tid >> 2,          sc0 = (tid & 3) * 8;
    int sr1 = (tid + 256) >> 2,  sc1 = ((tid + 256) & 3) * 8;

    auto stage = [&](int kc, int bb) {
        int k0 = kc * 32;
        cp16(&As[bb][sr0][sc0], ap + (size_t)sr0 * 1024 + k0 + sc0);
        cp16(&As[bb][sr1][sc1], ap + (size_t)sr1 * 1024 + k0 + sc1);
        cp16(&Bs[bb][sr0][sc0], bp + (size_t)sr0 * 1024 + k0 + sc0);
        cp_commit();
    };

    int t = lane >> 3;
    unsigned a_off = ((unsigned)((warp*16 + (t & 1)*8 + (lane & 7)) * 40
                                 + (t >> 1)*8)) * 2;
    unsigned b_off[4];
    #pragma unroll
    for (int np = 0; np < 4; np++)
        b_off[np] = ((unsigned)(((np*2 + (t >> 1))*8 + (lane & 7)) * 40
                                + (t & 1)*8)) * 2;

    unsigned asb[3], bsb[3];
    #pragma unroll
    for (int bb = 0; bb < 3; bb++) {
        asb[bb] = (unsigned)__cvta_generic_to_shared(&As[bb][0][0]);
        bsb[bb] = (unsigned)__cvta_generic_to_shared(&Bs[bb][0][0]);
    }

    auto compute = [&](unsigned as_base, unsigned bs_base) {
        #pragma unroll
        for (int kt = 0; kt < 2; kt++) {
            unsigned Af[4];
            ldsm4(Af[0], Af[1], Af[2], Af[3], as_base + a_off + kt*32);
            #pragma unroll
            for (int np = 0; np < 4; np++) {
                unsigned r0, r1, r2, r3;
                ldsm4(r0, r1, r2, r3, bs_base + b_off[np] + kt*32);
                mma_f16(acc[np*2    ], Af, r0, r1);
                mma_f16(acc[np*2 + 1], Af, r2, r3);
            }
        }
    };

    stage(0, 0);
    stage(1, 1);
    // main: kc = 0..26 in 9 groups of 3 (const buffer slots); each body:
    // wait(group kc done) -> barrier -> restage kc+2 -> compute kc
    for (int grp = 0; grp < 9; grp++) {
        int k = grp * 3;
        cp_wait<1>(); __syncthreads(); stage(k + 2, 2); compute(asb[0], bsb[0]);
        cp_wait<1>(); __syncthreads(); stage(k + 3, 0); compute(asb[1], bsb[1]);
        cp_wait<1>(); __syncthreads(); stage(k + 4, 1); compute(asb[2], bsb[2]);
    }
    // tail: kc = 27..31 (stages 29..31 issued here; none out of range)
    cp_wait<1>(); __syncthreads(); stage(29, 2); compute(asb[0], bsb[0]);  // kc=27
    cp_wait<1>(); __syncthreads(); stage(30, 0); compute(asb[1], bsb[1]);  // kc=28
    cp_wait<1>(); __syncthreads(); stage(31, 1); compute(asb[2], bsb[2]);  // kc=29
    cp_wait<1>(); __syncthreads();               compute(asb[0], bsb[0]);  // kc=30
    cp_wait<0>(); __syncthreads();               compute(asb[1], bsb[1]);  // kc=31

    #pragma unroll
    for (int nt = 0; nt < 8; nt++) {
        float2 v0 = make_float2(acc[nt][0], acc[nt][1]);
        float2 v1 = make_float2(acc[nt][2], acc[nt][3]);
        *(float2*)(C + (size_t)(m0 + warp*16 + g    ) * 1024 + n0 + nt*8 + 2*tg) = v0;
        *(float2*)(C + (size_t)(m0 + warp*16 + g + 8) * 1024 + n0 + nt*8 + 2*tg) = v1;
    }
}

// ---------------------------------------------------------------------------
extern "C" void kernel_launch(void* const* d_in, const int* in_sizes, int n_in,
                              void* d_out, int out_size)
{
    const float* x_q    = (const float*)d_in[0];
    const float* x_k    = (const float*)d_in[1];
    const float* x_v    = (const float*)d_in[2];
    const float* qn_w   = (const float*)d_in[3];
    const float* qn_b   = (const float*)d_in[4];
    const float* kn_w   = (const float*)d_in[5];
    const float* kn_b   = (const float*)d_in[6];
    const float* n_w    = (const float*)d_in[7];
    const float* n_b    = (const float*)d_in[8];
    const float* proj_w = (const float*)d_in[9];
    float* out = (float*)d_out;

    // 0.125 * log2(e): softmax in log2 domain (single EX2 per score)
    const float qscale = 0.125f * 1.4426950408889634f;

    ln64_kernel<<<(B_*H_*S_) / 16, 256>>>(x_q, qn_w, qn_b, qscale, B_*H_*S_, 0);
    ln64_kernel<<<(B_*N_) / 16, 256>>>(x_k, kn_w, kn_b, 1.0f, B_*N_, 1);
    tohalf_kernel<<<256, 256>>>(x_v, B_*N_*HD_/4, 0);
    tohalf_kernel<<<1024, 256>>>(proj_w, D_*D_/4, 1);

    attn_mma_kernel<<<dim3(S_/128, B_*H_), 128>>>();

    lnD_kernel<<<B_*S_, 256>>>(n_w, n_b);

    proj_mma_kernel<<<dim3(B_*S_/128, D_/64), 256>>>(out);
}

// round 17
// speedup vs baseline: 1.5067x; 1.0016x over previous
#include <cuda_runtime.h>
#include <cuda_fp16.h>

#define B_  4
#define S_  2048
#define N_  2048
#define D_  1024
#define H_  16
#define HD_ 64

// Scratch (allocation-free rule: __device__ globals)
__device__ __half g_qh[B_*H_*S_*HD_];  // LN'd, scaled 0.125*log2e, fp16
__device__ __half g_kh[B_*N_*HD_];     // LN'd K, fp16
__device__ __half g_vh[B_*N_*HD_];     // V fp16 (natural layout)
__device__ __half g_wh[D_*D_];         // proj W, fp16
__device__ __half g_oh[B_*H_*S_*HD_];  // attention output (B,H,S,HD) fp16
__device__ __half g_xh[B_*S_*D_];      // transposed + LN'd, fp16

// ---------------------------------------------------------------------------
// helpers
// ---------------------------------------------------------------------------
__device__ __forceinline__ float ex2(float x) {
    float y;
    asm("ex2.approx.ftz.f32 %0, %1;" : "=f"(y) : "f"(x));
    return y;
}
__device__ __forceinline__ unsigned packh2(float lo, float hi) {
    __half2 h = __floats2half2_rn(lo, hi);
    return *(unsigned*)&h;
}
__device__ __forceinline__ void mma_f16(float* c, const unsigned* a,
                                        unsigned b0, unsigned b1) {
    asm volatile(
        "mma.sync.aligned.m16n8k16.row.col.f32.f16.f16.f32 "
        "{%0,%1,%2,%3}, {%4,%5,%6,%7}, {%8,%9}, {%0,%1,%2,%3};"
        : "+f"(c[0]), "+f"(c[1]), "+f"(c[2]), "+f"(c[3])
        : "r"(a[0]), "r"(a[1]), "r"(a[2]), "r"(a[3]), "r"(b0), "r"(b1));
}
__device__ __forceinline__ void ldsm4(unsigned& r0, unsigned& r1, unsigned& r2,
                                      unsigned& r3, unsigned addr) {
    asm volatile("ldmatrix.sync.aligned.m8n8.x4.shared.b16 {%0,%1,%2,%3}, [%4];"
                 : "=r"(r0), "=r"(r1), "=r"(r2), "=r"(r3) : "r"(addr));
}
__device__ __forceinline__ void ldsm4t(unsigned& r0, unsigned& r1, unsigned& r2,
                                       unsigned& r3, unsigned addr) {
    asm volatile("ldmatrix.sync.aligned.m8n8.x4.trans.shared.b16 {%0,%1,%2,%3}, [%4];"
                 : "=r"(r0), "=r"(r1), "=r"(r2), "=r"(r3) : "r"(addr));
}
__device__ __forceinline__ void cp16(void* dst, const void* src) {
    unsigned d = (unsigned)__cvta_generic_to_shared(dst);
    asm volatile("cp.async.cg.shared.global [%0], [%1], 16;" :: "r"(d), "l"(src));
}
__device__ __forceinline__ void cp_commit() {
    asm volatile("cp.async.commit_group;");
}
template<int NN> __device__ __forceinline__ void cp_wait() {
    asm volatile("cp.async.wait_group %0;" :: "n"(NN));
}

// ---------------------------------------------------------------------------
// LayerNorm over rows of 64: 16 lanes per row (float4/lane), 2 rows per warp,
// 16 rows per 256-thread CTA. Fully 16B-coalesced. Writes fp16.
// ---------------------------------------------------------------------------
__global__ __launch_bounds__(256) void ln64_kernel(
    const float* __restrict__ x, const float* __restrict__ w,
    const float* __restrict__ bias, float scale, int nrows, int which)
{
    int row = blockIdx.x * 16 + (threadIdx.x >> 4);
    if (row >= nrows) return;
    int l16 = threadIdx.x & 15;
    float4 v = ((const float4*)(x + (size_t)row * 64))[l16];
    float s = v.x + v.y + v.z + v.w;
    #pragma unroll
    for (int m = 8; m; m >>= 1) s += __shfl_xor_sync(0xffffffffu, s, m);
    float mean = s * (1.0f / 64.0f);
    float a0 = v.x - mean, a1 = v.y - mean, a2 = v.z - mean, a3 = v.w - mean;
    float q2 = a0*a0 + a1*a1 + a2*a2 + a3*a3;
    #pragma unroll
    for (int m = 8; m; m >>= 1) q2 += __shfl_xor_sync(0xffffffffu, q2, m);
    float inv = rsqrtf(q2 * (1.0f / 64.0f) + 1e-5f);
    float4 wv = ((const float4*)w)[l16];
    float4 bv = ((const float4*)bias)[l16];
    uint2 o;
    o.x = packh2((a0 * inv * wv.x + bv.x) * scale, (a1 * inv * wv.y + bv.y) * scale);
    o.y = packh2((a2 * inv * wv.z + bv.z) * scale, (a3 * inv * wv.w + bv.w) * scale);
    __half* dst = which ? g_kh : g_qh;
    ((uint2*)(dst + (size_t)row * 64))[l16] = o;
}

// ---------------------------------------------------------------------------
// f32 -> fp16 convert. which==0 -> g_vh, which==1 -> g_wh
// ---------------------------------------------------------------------------
__global__ __launch_bounds__(256) void tohalf_kernel(
    const float* __restrict__ src, int n4, int which)
{
    __half* dst = which ? g_wh : g_vh;
    for (int i4 = blockIdx.x * 256 + threadIdx.x; i4 < n4; i4 += gridDim.x * 256) {
        float4 t = ((const float4*)src)[i4];
        uint2 o;
        o.x = packh2(t.x, t.y);
        o.y = packh2(t.z, t.w);
        ((uint2*)dst)[i4] = o;
    }
}

// ---------------------------------------------------------------------------
// Flash attention: fp16 m16n8k16, 32 queries/warp, 4 warps / 128 threads,
// minBlocks=3, grid (S/128, B*H). FMA-pipe rowsum; 3-STAGE const-slot
// cp.async pipeline with ONE barrier per chunk (proj-proven pattern:
// wait<1> -> sync -> restage slot(kc-1) -> compute slot(kc)).
// Smem = 3 * 64*72*2 * 2 = 55296 B (3 CTAs/SM: 166KB < 228KB). fp16 out.
// ---------------------------------------------------------------------------
__global__ __launch_bounds__(128, 3) void attn_mma_kernel()
{
    __shared__ __half Ks[3][64][72];
    __shared__ __half Vs[3][64][72];

    int bh = blockIdx.y;
    int b  = bh >> 4;
    int tid  = threadIdx.x;
    int warp = tid >> 5, lane = tid & 31;
    int g = lane >> 2, tg = lane & 3;

    const __half* kp = g_kh + (size_t)b * N_ * 64;
    const __half* vp = g_vh + (size_t)b * N_ * 64;

    const __half* qp = g_qh + ((size_t)bh * S_ + blockIdx.x * 128 + warp * 32) * 64;
    unsigned Qf[2][4][4];
    #pragma unroll
    for (int m = 0; m < 2; m++) {
        #pragma unroll
        for (int kt = 0; kt < 4; kt++) {
            Qf[m][kt][0] = *(const unsigned*)(qp + (size_t)(m*16 + g     ) * 64 + kt*16 + 2*tg);
            Qf[m][kt][1] = *(const unsigned*)(qp + (size_t)(m*16 + g + 8 ) * 64 + kt*16 + 2*tg);
            Qf[m][kt][2] = *(const unsigned*)(qp + (size_t)(m*16 + g     ) * 64 + kt*16 + 8 + 2*tg);
            Qf[m][kt][3] = *(const unsigned*)(qp + (size_t)(m*16 + g + 8 ) * 64 + kt*16 + 8 + 2*tg);
        }
    }

    float Oa[2][8][4];
    #pragma unroll
    for (int m = 0; m < 2; m++)
        #pragma unroll
        for (int i = 0; i < 8; i++)
            #pragma unroll
            for (int j = 0; j < 4; j++) Oa[m][i][j] = 0.0f;
    float rs[2][2] = {{0.0f, 0.0f}, {0.0f, 0.0f}};  // rowsums: [m][row g / g+8]

    // hoisted staging coordinates: 1024 cp16 / 128 threads = 8 per thread
    auto stage = [&](int kc, int bb) {
        #pragma unroll
        for (int j = 0; j < 8; j++) {
            int i = tid + 128 * j;           // 0..1023
            if (i < 512) {
                int r = i >> 3, c = i & 7;
                cp16(&Ks[bb][r][c * 8], kp + ((size_t)kc * 64 + r) * 64 + c * 8);
            } else {
                int i2 = i - 512;
                int r = i2 >> 3, c = i2 & 7;
                cp16(&Vs[bb][r][c * 8], vp + ((size_t)kc * 64 + r) * 64 + c * 8);
            }
        }
        cp_commit();
    };

    // hoisted fragment offsets within a buffer
    unsigned k_off[8], v_off[8];
    #pragma unroll
    for (int nt = 0; nt < 8; nt++) {
        k_off[nt] = ((unsigned)((nt*8 + (lane & 7)) * 72 + (lane >> 3) * 8)) * 2;
        v_off[nt] = ((unsigned)(((lane >> 3) * 8 + (lane & 7)) * 72 + nt * 8)) * 2;
    }
    unsigned ksb[3], vsb[3];
    #pragma unroll
    for (int bb = 0; bb < 3; bb++) {
        ksb[bb] = (unsigned)__cvta_generic_to_shared(&Ks[bb][0][0]);
        vsb[bb] = (unsigned)__cvta_generic_to_shared(&Vs[bb][0][0]);
    }

    auto compute = [&](unsigned ks_base, unsigned vs_base) {
        unsigned Pf[2][4][4];
        #pragma unroll
        for (int ntp = 0; ntp < 4; ntp++) {
            float sc[2][2][4];
            #pragma unroll
            for (int sub = 0; sub < 2; sub++) {
                int nt = ntp * 2 + sub;
                #pragma unroll
                for (int m = 0; m < 2; m++)
                    sc[m][sub][0] = sc[m][sub][1] = sc[m][sub][2] = sc[m][sub][3] = 0.0f;
                unsigned a0 = ks_base + k_off[nt];
                unsigned r0, r1, r2, r3;
                ldsm4(r0, r1, r2, r3, a0);            // kt0, kt1
                #pragma unroll
                for (int m = 0; m < 2; m++) {
                    mma_f16(sc[m][sub], Qf[m][0], r0, r1);
                    mma_f16(sc[m][sub], Qf[m][1], r2, r3);
                }
                ldsm4(r0, r1, r2, r3, a0 + 64);       // kt2, kt3
                #pragma unroll
                for (int m = 0; m < 2; m++) {
                    mma_f16(sc[m][sub], Qf[m][2], r0, r1);
                    mma_f16(sc[m][sub], Qf[m][3], r2, r3);
                }
            }
            #pragma unroll
            for (int m = 0; m < 2; m++) {
                #pragma unroll
                for (int sub = 0; sub < 2; sub++) {
                    sc[m][sub][0] = ex2(sc[m][sub][0]);
                    sc[m][sub][1] = ex2(sc[m][sub][1]);
                    sc[m][sub][2] = ex2(sc[m][sub][2]);
                    sc[m][sub][3] = ex2(sc[m][sub][3]);
                }
                rs[m][0] += (sc[m][0][0] + sc[m][0][1]) + (sc[m][1][0] + sc[m][1][1]);
                rs[m][1] += (sc[m][0][2] + sc[m][0][3]) + (sc[m][1][2] + sc[m][1][3]);
                Pf[m][ntp][0] = packh2(sc[m][0][0], sc[m][0][1]);
                Pf[m][ntp][1] = packh2(sc[m][0][2], sc[m][0][3]);
                Pf[m][ntp][2] = packh2(sc[m][1][0], sc[m][1][1]);
                Pf[m][ntp][3] = packh2(sc[m][1][2], sc[m][1][3]);
            }
        }

        #pragma unroll
        for (int nt = 0; nt < 8; nt++) {
            unsigned a0 = vs_base + v_off[nt];
            unsigned r0, r1, r2, r3;
            ldsm4t(r0, r1, r2, r3, a0);                    // keys 0..31
            #pragma unroll
            for (int m = 0; m < 2; m++) {
                mma_f16(Oa[m][nt], Pf[m][0], r0, r1);
                mma_f16(Oa[m][nt], Pf[m][1], r2, r3);
            }
            ldsm4t(r0, r1, r2, r3, a0 + 32 * 72 * 2);      // keys 32..63
            #pragma unroll
            for (int m = 0; m < 2; m++) {
                mma_f16(Oa[m][nt], Pf[m][2], r0, r1);
                mma_f16(Oa[m][nt], Pf[m][3], r2, r3);
            }
        }
    };

    stage(0, 0);
    stage(1, 1);
    // main: kc = 0..29 in 10 groups of 3, const buffer slots; one barrier per
    // chunk. At body kc: committed kc+2 groups, wait<1> -> 0..kc done; the
    // restage targets slot((kc+2)%3) = slot of compute kc-1 (barrier-proven).
    for (int grp = 0; grp < 10; grp++) {
        int k = grp * 3;
        cp_wait<1>(); __syncthreads(); if (k + 2 < 32) stage(k + 2, 2); compute(ksb[0], vsb[0]);
        cp_wait<1>(); __syncthreads(); if (k + 3 < 32) stage(k + 3, 0); compute(ksb[1], vsb[1]);
        cp_wait<1>(); __syncthreads(); if (k + 4 < 32) stage(k + 4, 1); compute(ksb[2], vsb[2]);
    }
    // tail: kc=30 (slot0), kc=31 (slot1); stages already issued
    cp_wait<1>(); __syncthreads(); compute(ksb[0], vsb[0]);
    cp_wait<0>(); __syncthreads(); compute(ksb[1], vsb[1]);

    // epilogue: quad-reduce rowsums once; normalize; fp16 store
    __half* op = g_oh + ((size_t)bh * S_ + blockIdx.x * 128 + warp * 32) * 64;
    #pragma unroll
    for (int m = 0; m < 2; m++) {
        float s0 = rs[m][0], s1 = rs[m][1];
        s0 += __shfl_xor_sync(0xffffffffu, s0, 1);
        s0 += __shfl_xor_sync(0xffffffffu, s0, 2);
        s1 += __shfl_xor_sync(0xffffffffu, s1, 1);
        s1 += __shfl_xor_sync(0xffffffffu, s1, 2);
        float inv0 = 1.0f / s0, inv1 = 1.0f / s1;
        #pragma unroll
        for (int nt = 0; nt < 8; nt++) {
            unsigned v0 = packh2(Oa[m][nt][0] * inv0, Oa[m][nt][1] * inv0);
            unsigned v1 = packh2(Oa[m][nt][2] * inv1, Oa[m][nt][3] * inv1);
            *(unsigned*)(op + (size_t)(m*16 + g     ) * 64 + nt*8 + 2*tg) = v0;
            *(unsigned*)(op + (size_t)(m*16 + g + 8 ) * 64 + nt*8 + 2*tg) = v1;
        }
    }
}

// ---------------------------------------------------------------------------
// Gather fp16 (B,H,S,HD) -> (B,S,D) + LayerNorm over D=1024 -> fp16 output.
// ---------------------------------------------------------------------------
__global__ __launch_bounds__(256) void lnD_kernel(
    const float* __restrict__ w, const float* __restrict__ bias)
{
    int bs = blockIdx.x;
    int b = bs >> 11, s = bs & 2047;
    int tid = threadIdx.x;
    int d = tid * 4;
    int h = d >> 6, hd = d & 63;
    uint2 raw = *(const uint2*)(g_oh + (((size_t)(b * H_ + h) * S_ + s) * 64 + hd));
    float2 p0 = __half22float2(*(__half2*)&raw.x);
    float2 p1 = __half22float2(*(__half2*)&raw.y);
    float v0 = p0.x, v1 = p0.y, v2 = p1.x, v3 = p1.y;

    __shared__ float r1[8], r2[8];
    float sum = v0 + v1 + v2 + v3;
    #pragma unroll
    for (int m = 16; m; m >>= 1) sum += __shfl_xor_sync(0xffffffffu, sum, m);
    if ((tid & 31) == 0) r1[tid >> 5] = sum;
    __syncthreads();
    float tot = 0.0f;
    #pragma unroll
    for (int i = 0; i < 8; i++) tot += r1[i];
    float mean = tot * (1.0f / 1024.0f);

    float a0 = v0 - mean, a1 = v1 - mean, a2 = v2 - mean, a3 = v3 - mean;
    float sq = a0*a0 + a1*a1 + a2*a2 + a3*a3;
    #pragma unroll
    for (int m = 16; m; m >>= 1) sq += __shfl_xor_sync(0xffffffffu, sq, m);
    if ((tid & 31) == 0) r2[tid >> 5] = sq;
    __syncthreads();
    float tot2 = 0.0f;
    #pragma unroll
    for (int i = 0; i < 8; i++) tot2 += r2[i];
    float inv = rsqrtf(tot2 * (1.0f / 1024.0f) + 1e-5f);

    float4 wv = *(const float4*)(w + d);
    float4 bv = *(const float4*)(bias + d);
    uint2 o;
    o.x = packh2(a0 * inv * wv.x + bv.x, a1 * inv * wv.y + bv.y);
    o.y = packh2(a2 * inv * wv.z + bv.z, a3 * inv * wv.w + bv.w);
    *(uint2*)(g_xh + (size_t)bs * 1024 + d) = o;
}

// ---------------------------------------------------------------------------
// Projection: fp16 m16n8k16 + ldmatrix, 3-stage const-slot cp.async pipeline,
// single __syncthreads per body. CTA tile 128x64, 256 threads, k-chunk 32.
// Smem = 3*(128+64)*40*2 = 46080 B.
// ---------------------------------------------------------------------------
__global__ __launch_bounds__(256) void proj_mma_kernel(float* __restrict__ C)
{
    __shared__ __half As[3][128][40];
    __shared__ __half Bs[3][64][40];

    int m0 = blockIdx.x * 128, n0 = blockIdx.y * 64;
    int tid  = threadIdx.x;
    int warp = tid >> 5, lane = tid & 31;
    int g = lane >> 2, tg = lane & 3;

    const __half* ap = g_xh + (size_t)m0 * 1024;
    const __half* bp = g_wh + (size_t)n0 * 1024;

    float acc[8][4];
    #pragma unroll
    for (int i = 0; i < 8; i++)
        #pragma unroll
        for (int j = 0; j < 4; j++) acc[i][j] = 0.0f;

    int sr0 = tid >> 2,          sc0 = (tid & 3) * 8;
    int sr1 = (tid + 256) >> 2,  sc1 = ((tid + 256) & 3) * 8;

    auto stage = [&](int kc, int bb) {
        int k0 = kc * 32;
        cp16(&As[bb][sr0][sc0], ap + (size_t)sr0 * 1024 + k0 + sc0);
        cp16(&As[bb][sr1][sc1], ap + (size_t)sr1 * 1024 + k0 + sc1);
        cp16(&Bs[bb][sr0][sc0], bp + (size_t)sr0 * 1024 + k0 + sc0);
        cp_commit();
    };

    int t = lane >> 3;
    unsigned a_off = ((unsigned)((warp*16 + (t & 1)*8 + (lane & 7)) * 40
                                 + (t >> 1)*8)) * 2;
    unsigned b_off[4];
    #pragma unroll
    for (int np = 0; np < 4; np++)
        b_off[np] = ((unsigned)(((np*2 + (t >> 1))*8 + (lane & 7)) * 40
                                + (t & 1)*8)) * 2;

    unsigned asb[3], bsb[3];
    #pragma unroll
    for (int bb = 0; bb < 3; bb++) {
        asb[bb] = (unsigned)__cvta_generic_to_shared(&As[bb][0][0]);
        bsb[bb] = (unsigned)__cvta_generic_to_shared(&Bs[bb][0][0]);
    }

    auto compute = [&](unsigned as_base, unsigned bs_base) {
        #pragma unroll
        for (int kt = 0; kt < 2; kt++) {
            unsigned Af[4];
            ldsm4(Af[0], Af[1], Af[2], Af[3], as_base + a_off + kt*32);
            #pragma unroll
            for (int np = 0; np < 4; np++) {
                unsigned r0, r1, r2, r3;
                ldsm4(r0, r1, r2, r3, bs_base + b_off[np] + kt*32);
                mma_f16(acc[np*2    ], Af, r0, r1);
                mma_f16(acc[np*2 + 1], Af, r2, r3);
            }
        }
    };

    stage(0, 0);
    stage(1, 1);
    for (int grp = 0; grp < 9; grp++) {
        int k = grp * 3;
        cp_wait<1>(); __syncthreads(); stage(k + 2, 2); compute(asb[0], bsb[0]);
        cp_wait<1>(); __syncthreads(); stage(k + 3, 0); compute(asb[1], bsb[1]);
        cp_wait<1>(); __syncthreads(); stage(k + 4, 1); compute(asb[2], bsb[2]);
    }
    cp_wait<1>(); __syncthreads(); stage(29, 2); compute(asb[0], bsb[0]);  // kc=27
    cp_wait<1>(); __syncthreads(); stage(30, 0); compute(asb[1], bsb[1]);  // kc=28
    cp_wait<1>(); __syncthreads(); stage(31, 1); compute(asb[2], bsb[2]);  // kc=29
    cp_wait<1>(); __syncthreads();               compute(asb[0], bsb[0]);  // kc=30
    cp_wait<0>(); __syncthreads();               compute(asb[1], bsb[1]);  // kc=31

    #pragma unroll
    for (int nt = 0; nt < 8; nt++) {
        float2 v0 = make_float2(acc[nt][0], acc[nt][1]);
        float2 v1 = make_float2(acc[nt][2], acc[nt][3]);
        *(float2*)(C + (size_t)(m0 + warp*16 + g    ) * 1024 + n0 + nt*8 + 2*tg) = v0;
        *(float2*)(C + (size_t)(m0 + warp*16 + g + 8) * 1024 + n0 + nt*8 + 2*tg) = v1;
    }
}

// ---------------------------------------------------------------------------
extern "C" void kernel_launch(void* const* d_in, const int* in_sizes, int n_in,
                              void* d_out, int out_size)
{
    const float* x_q    = (const float*)d_in[0];
    const float* x_k    = (const float*)d_in[1];
    const float* x_v    = (const float*)d_in[2];
    const float* qn_w   = (const float*)d_in[3];
    const float* qn_b   = (const float*)d_in[4];
    const float* kn_w   = (const float*)d_in[5];
    const float* kn_b   = (const float*)d_in[6];
    const float* n_w    = (const float*)d_in[7];
    const float* n_b    = (const float*)d_in[8];
    const float* proj_w = (const float*)d_in[9];
    float* out = (float*)d_out;

    // 0.125 * log2(e): softmax in log2 domain (single EX2 per score)
    const float qscale = 0.125f * 1.4426950408889634f;

    ln64_kernel<<<(B_*H_*S_) / 16, 256>>>(x_q, qn_w, qn_b, qscale, B_*H_*S_, 0);
    ln64_kernel<<<(B_*N_) / 16, 256>>>(x_k, kn_w, kn_b, 1.0f, B_*N_, 1);
    tohalf_kernel<<<256, 256>>>(x_v, B_*N_*HD_/4, 0);
    tohalf_kernel<<<1024, 256>>>(proj_w, D_*D_/4, 1);

    attn_mma_kernel<<<dim3(S_/128, B_*H_), 128>>>();

    lnD_kernel<<<B_*S_, 256>>>(n_w, n_b);

    proj_mma_kernel<<<dim3(B_*S_/128, D_/64), 256>>>(out);
}